// round 11
// baseline (speedup 1.0000x reference)
#include <cuda_runtime.h>
#include <cuda_bf16.h>
#include <cuda_fp16.h>
#include <math.h>
#include <stdint.h>

#define DM   1024
#define NH   16
#define DFF  4096
#define BB   8
#define SS   1024
#define MTOK (BB*SS)

// ---------------- scratch ----------------
__device__ float g_x0  [MTOK*DM];
__device__ __nv_bfloat16 g_qkvh[(size_t)MTOK*3*DM];
__device__ float g_res1[MTOK*DM];   // x0 + proj (pre-LN1)
__device__ float g_x1  [MTOK*DM];
__device__ float g_res2[MTOK*DM];   // x1 + ffn (pre-LN2)
__device__ __half g_x0s  [(size_t)MTOK*DM];
__device__ __half g_attns[(size_t)MTOK*DM];
__device__ __half g_x1s  [(size_t)MTOK*DM];
__device__ __half g_hs   [(size_t)MTOK*DFF];
__device__ __half g_wqkvs[(size_t)(3*DM)*DM];
__device__ __half g_wouts[(size_t)DM*DM];
__device__ __half g_w1s  [(size_t)DFF*DM];
__device__ __half g_w2s  [(size_t)DM*DFF];

// ---------------- asm helpers ----------------
__device__ __forceinline__ uint32_t smem_u32(const void* p) {
    uint32_t a;
    asm("{ .reg .u64 t; cvta.to.shared.u64 t, %1; cvt.u32.u64 %0, t; }" : "=r"(a) : "l"(p));
    return a;
}
#define CP_ASYNC16(saddr, gptr) \
    asm volatile("cp.async.cg.shared.global [%0], [%1], 16;" :: "r"(saddr), "l"(gptr))
#define CP_COMMIT() asm volatile("cp.async.commit_group;" ::: "memory")
#define CP_WAIT1()  asm volatile("cp.async.wait_group 1;" ::: "memory")
#define CP_WAIT0()  asm volatile("cp.async.wait_group 0;" ::: "memory")

#define LDM_X4(r0, r1, r2, r3, a) \
    asm volatile("ldmatrix.sync.aligned.m8n8.x4.shared.b16 {%0,%1,%2,%3}, [%4];" \
                 : "=r"(r0), "=r"(r1), "=r"(r2), "=r"(r3) : "r"(a))
#define LDM_X4T(r0, r1, r2, r3, a) \
    asm volatile("ldmatrix.sync.aligned.m8n8.x4.trans.shared.b16 {%0,%1,%2,%3}, [%4];" \
                 : "=r"(r0), "=r"(r1), "=r"(r2), "=r"(r3) : "r"(a))

#define MMA_F16(d, a0, a1, a2, a3, b0, b1) \
    asm volatile("mma.sync.aligned.m16n8k16.row.col.f32.f16.f16.f32 " \
                 "{%0,%1,%2,%3}, {%4,%5,%6,%7}, {%8,%9}, {%0,%1,%2,%3};" \
                 : "+f"((d)[0]), "+f"((d)[1]), "+f"((d)[2]), "+f"((d)[3]) \
                 : "r"(a0), "r"(a1), "r"(a2), "r"(a3), "r"(b0), "r"(b1))
#define MMA_BF16(d, a0, a1, a2, a3, b0, b1) \
    asm volatile("mma.sync.aligned.m16n8k16.row.col.f32.bf16.bf16.f32 " \
                 "{%0,%1,%2,%3}, {%4,%5,%6,%7}, {%8,%9}, {%0,%1,%2,%3};" \
                 : "+f"((d)[0]), "+f"((d)[1]), "+f"((d)[2]), "+f"((d)[3]) \
                 : "r"(a0), "r"(a1), "r"(a2), "r"(a3), "r"(b0), "r"(b1))

__device__ __forceinline__ float gelu_exact(float v) {
    return 0.5f * v * (1.0f + erff(v * 0.70710678118654752f));
}
__device__ __forceinline__ uint32_t pack_bf162(float lo, float hi) {
    __nv_bfloat162 t = __floats2bfloat162_rn(lo, hi);
    return *(uint32_t*)&t;
}

// ---------------- GEMM via mma.sync (fp16, f32 accum) --------------------
// CTA 128x128, BK=64, 3-stage cp.async pipeline, 8 warps of 64x32.
// ACT=0: f32 out = acc + bias + res[row,col]. ACT=1: half gelu out. ACT=2: bf16 out
// (Q cols pre-scaled 0.125).
#define ROWB    144
#define STG_B   (128 * ROWB)
#define NSTAGE  3
#define GSMEM   (NSTAGE * STG_B * 2)

template <int ACT>
__global__ void __launch_bounds__(256, 2)
gemm_mma(const __half* __restrict__ A, const __half* __restrict__ B,
         const float* __restrict__ bias, const float* __restrict__ res,
         float* __restrict__ Cf, void* __restrict__ Cx, int Ndim, int Kp)
{
    extern __shared__ __align__(128) char smem[];
    const uint32_t sA = smem_u32(smem);
    const uint32_t sB = sA + NSTAGE * STG_B;

    const int tid  = threadIdx.x;
    const int lane = tid & 31;
    const int wid  = tid >> 5;
    const int wm   = wid & 1;
    const int wn   = wid >> 1;
    const int row0 = blockIdx.y * 128;
    const int n0   = blockIdx.x * 128;

    const uint32_t aLd = sA + (wm * 64 + (lane & 15)) * ROWB + (lane >> 4) * 16;
    const uint32_t bLd = sB + (wn * 32 + (lane & 15)) * ROWB + (lane >> 4) * 16;

    float d[4][4][4];
#pragma unroll
    for (int i = 0; i < 4; i++)
#pragma unroll
        for (int j = 0; j < 4; j++)
#pragma unroll
            for (int c = 0; c < 4; c++) d[i][j][c] = 0.f;

    const int kTiles = Kp >> 6;

    auto load_stage = [&](int kt, int s) {
        const int k0 = kt * 64;
        const uint32_t dA = sA + s * STG_B;
        const uint32_t dB = sB + s * STG_B;
#pragma unroll
        for (int j = 0; j < 4; j++) {
            int id = tid + 256 * j;
            int r = id >> 3;
            int cb = (id & 7) * 16;
            CP_ASYNC16(dA + r * ROWB + cb,
                       (const char*)(A + (size_t)(row0 + r) * Kp + k0) + cb);
            CP_ASYNC16(dB + r * ROWB + cb,
                       (const char*)(B + (size_t)(n0 + r) * Kp + k0) + cb);
        }
        CP_COMMIT();
    };

    load_stage(0, 0);
    load_stage(1, 1);

    for (int kt = 0; kt < kTiles; kt++) {
        CP_WAIT1();
        __syncthreads();   // also protects stage (kt+2)%3 from kt-1 readers

        if (kt + 2 < kTiles) {
            load_stage(kt + 2, (kt + 2) % NSTAGE);
        } else {
            CP_COMMIT();
        }

        const int st = kt % NSTAGE;
        const uint32_t aS = aLd + st * STG_B;
        const uint32_t bS = bLd + st * STG_B;
#pragma unroll
        for (int k16 = 0; k16 < 4; k16++) {
            uint32_t a[4][4], b[4][2];
#pragma unroll
            for (int mt = 0; mt < 4; mt++)
                LDM_X4(a[mt][0], a[mt][1], a[mt][2], a[mt][3],
                       aS + mt * (16 * ROWB) + k16 * 32);
#pragma unroll
            for (int p = 0; p < 2; p++) {
                uint32_t r0, r1, r2, r3;
                LDM_X4(r0, r1, r2, r3, bS + p * (16 * ROWB) + k16 * 32);
                b[p * 2 + 0][0] = r0; b[p * 2 + 0][1] = r2;
                b[p * 2 + 1][0] = r1; b[p * 2 + 1][1] = r3;
            }
#pragma unroll
            for (int mt = 0; mt < 4; mt++)
#pragma unroll
                for (int nt = 0; nt < 4; nt++)
                    MMA_F16(d[mt][nt], a[mt][0], a[mt][1], a[mt][2], a[mt][3],
                            b[nt][0], b[nt][1]);
        }
    }
    CP_WAIT0();

#pragma unroll
    for (int mt = 0; mt < 4; mt++) {
#pragma unroll
        for (int half = 0; half < 2; half++) {
            const int row = row0 + wm * 64 + mt * 16 + (lane >> 2) + half * 8;
#pragma unroll
            for (int nt = 0; nt < 4; nt++) {
                const int col = n0 + wn * 32 + nt * 8 + (lane & 3) * 2;
                float v0 = d[mt][nt][half * 2 + 0] + bias[col];
                float v1 = d[mt][nt][half * 2 + 1] + bias[col + 1];
                if (ACT == 0) {
                    float2 rr = *(const float2*)&res[(size_t)row * Ndim + col];
                    float2 o; o.x = v0 + rr.x; o.y = v1 + rr.y;
                    *(float2*)&Cf[(size_t)row * Ndim + col] = o;
                } else if (ACT == 1) {
                    v0 = gelu_exact(v0);
                    v1 = gelu_exact(v1);
                    __half2 hp;
                    hp.x = __float2half_rn(v0);
                    hp.y = __float2half_rn(v1);
                    *(__half2*)&((__half*)Cx)[(size_t)row * Ndim + col] = hp;
                } else {
                    const float sc = (col < 1024) ? 0.125f : 1.0f;
                    __nv_bfloat162 hp = __floats2bfloat162_rn(v0 * sc, v1 * sc);
                    *(__nv_bfloat162*)&((__nv_bfloat16*)Cx)[(size_t)row * Ndim + col] = hp;
                }
            }
        }
    }
}

// -------- weight transpose to fp16: W[K,N] -> Wt[N,K] --------
__global__ void wconv_kernel(const float* __restrict__ W, __half* __restrict__ Wt,
                             int K, int N)
{
    __shared__ float t[32][33];
    const int n0 = blockIdx.x * 32, k0 = blockIdx.y * 32;
#pragma unroll
    for (int i = threadIdx.y; i < 32; i += 8)
        t[i][threadIdx.x] = W[(size_t)(k0 + i) * N + n0 + threadIdx.x];
    __syncthreads();
#pragma unroll
    for (int i = threadIdx.y; i < 32; i += 8) {
        int n = n0 + i, k = k0 + threadIdx.x;
        Wt[(size_t)n * K + k] = __float2half_rn(t[threadIdx.x][i]);
    }
}

// -------- add step embed; fp16 copy --------
__global__ void add_step_kernel(const float* __restrict__ x, const float* __restrict__ se,
                                const int* __restrict__ ts, float* __restrict__ x0,
                                __half* __restrict__ xs)
{
    int i = blockIdx.x * blockDim.x + threadIdx.x;
    int step = ts[0];
    if (step > 15) step = 15;
    if (step < 0) step += 16;
    int k = i & (DM - 1);
    float v = x[i] + se[step * DM + k];
    x0[i] = v;
    xs[i] = __float2half_rn(v);
}

// ---------------- flash attention on tensor cores (bf16 in, bf16 mma) -----------
#define ASTRIDE 72
#define KVB (64 * ASTRIDE * 2)
__global__ void __launch_bounds__(128)
attn_mma_kernel(const __nv_bfloat16* __restrict__ qkvh, const float* __restrict__ rpb,
                __half* __restrict__ outs)
{
    __shared__ __nv_bfloat16 Qs[64 * ASTRIDE];
    __shared__ __nv_bfloat16 Kst[2][64 * ASTRIDE];
    __shared__ __nv_bfloat16 Vst[2][64 * ASTRIDE];
    __shared__ float rb[128];

    const int tid = threadIdx.x;
    const int lane = tid & 31;
    const int w = tid >> 5;
    const int qt = blockIdx.x, h = blockIdx.y, b = blockIdx.z;
    const int qbase = qt * 64;

    if (tid < 127) rb[tid] = rpb[tid];

    {
        int r = tid >> 1;
        int c0 = (tid & 1) * 32;
        const uint4* src = (const uint4*)(qkvh + ((size_t)(b * SS + qbase + r)) * 3072 + h * 64 + c0);
        uint4* dst = (uint4*)&Qs[r * ASTRIDE + c0];
#pragma unroll
        for (int j = 0; j < 4; j++) dst[j] = src[j];
    }

    const uint32_t sQ = smem_u32(Qs);
    const uint32_t sK0 = smem_u32(Kst);
    const uint32_t sV0 = smem_u32(Vst);
    const uint32_t aQ = sQ + (w * 16 + (lane & 15)) * (ASTRIDE * 2) + (lane >> 4) * 16;
    const uint32_t bKV = (((lane >> 3) & 1) * 8 + (lane & 7)) * (ASTRIDE * 2) + (lane >> 4) * 16;

    auto load_kv = [&](int kt, int st) {
#pragma unroll
        for (int j = 0; j < 4; j++) {
            int id = tid + 128 * j;
            int r = id >> 3;
            int cb = (id & 7) * 8;
            const char* gsrc = (const char*)(qkvh + ((size_t)(b * SS + kt * 64 + r)) * 3072 + h * 64 + cb);
            CP_ASYNC16(sK0 + st * KVB + r * (ASTRIDE * 2) + cb * 2, gsrc + 2048);
            CP_ASYNC16(sV0 + st * KVB + r * (ASTRIDE * 2) + cb * 2, gsrc + 4096);
        }
        CP_COMMIT();
    };

    load_kv(0, 0);

    float m0 = -1e30f, m1 = -1e30f, l0 = 0.f, l1 = 0.f;
    float o[8][4];
#pragma unroll
    for (int nt = 0; nt < 8; nt++)
#pragma unroll
        for (int j = 0; j < 4; j++) o[nt][j] = 0.f;

    const int r0 = lane >> 2;
    const int cql = (lane & 3) * 2;
    const int qg0 = qbase + w * 16 + r0;

    for (int kt = 0; kt < 16; kt++) {
        const int st = kt & 1;
        if (kt + 1 < 16) {
            load_kv(kt + 1, st ^ 1);
            CP_WAIT1();
        } else {
            CP_WAIT0();
        }
        __syncthreads();

        const uint32_t sK = sK0 + st * KVB;
        const uint32_t sV = sV0 + st * KVB;

        float s[8][4];
#pragma unroll
        for (int nt = 0; nt < 8; nt++)
#pragma unroll
            for (int j = 0; j < 4; j++) s[nt][j] = 0.f;
#pragma unroll
        for (int k16 = 0; k16 < 4; k16++) {
            uint32_t a0, a1, a2, a3;
            LDM_X4(a0, a1, a2, a3, aQ + k16 * 32);
#pragma unroll
            for (int np = 0; np < 4; np++) {
                uint32_t b0, b1, b2, b3;
                LDM_X4(b0, b1, b2, b3, sK + bKV + np * (16 * ASTRIDE * 2) + k16 * 32);
                MMA_BF16(s[np * 2],     a0, a1, a2, a3, b0, b2);
                MMA_BF16(s[np * 2 + 1], a0, a1, a2, a3, b1, b3);
            }
        }

        const int kb = kt * 64 + cql;
        float mt0 = -1e30f, mt1 = -1e30f;
#pragma unroll
        for (int nt = 0; nt < 8; nt++) {
            int kg = kb + nt * 8;
            int i00 = min(max(qg0 - kg + 63, 0), 126);
            int i01 = min(max(qg0 - kg + 62, 0), 126);
            int i10 = min(max(qg0 - kg + 71, 0), 126);
            int i11 = min(max(qg0 - kg + 70, 0), 126);
            s[nt][0] += rb[i00]; s[nt][1] += rb[i01];
            s[nt][2] += rb[i10]; s[nt][3] += rb[i11];
            mt0 = fmaxf(mt0, fmaxf(s[nt][0], s[nt][1]));
            mt1 = fmaxf(mt1, fmaxf(s[nt][2], s[nt][3]));
        }
        mt0 = fmaxf(mt0, __shfl_xor_sync(0xffffffffu, mt0, 1));
        mt0 = fmaxf(mt0, __shfl_xor_sync(0xffffffffu, mt0, 2));
        mt1 = fmaxf(mt1, __shfl_xor_sync(0xffffffffu, mt1, 1));
        mt1 = fmaxf(mt1, __shfl_xor_sync(0xffffffffu, mt1, 2));

        float mn0 = fmaxf(m0, mt0), mn1 = fmaxf(m1, mt1);
        float c0f = __expf(m0 - mn0), c1f = __expf(m1 - mn1);
        float ls0 = 0.f, ls1 = 0.f;
        uint32_t pa[4][4];
#pragma unroll
        for (int nt = 0; nt < 8; nt++) {
            float p0 = __expf(s[nt][0] - mn0);
            float p1 = __expf(s[nt][1] - mn0);
            float p2 = __expf(s[nt][2] - mn1);
            float p3 = __expf(s[nt][3] - mn1);
            ls0 += p0 + p1; ls1 += p2 + p3;
            uint32_t lo = pack_bf162(p0, p1);
            uint32_t hi = pack_bf162(p2, p3);
            if ((nt & 1) == 0) { pa[nt >> 1][0] = lo; pa[nt >> 1][1] = hi; }
            else               { pa[nt >> 1][2] = lo; pa[nt >> 1][3] = hi; }
        }
        ls0 += __shfl_xor_sync(0xffffffffu, ls0, 1);
        ls0 += __shfl_xor_sync(0xffffffffu, ls0, 2);
        ls1 += __shfl_xor_sync(0xffffffffu, ls1, 1);
        ls1 += __shfl_xor_sync(0xffffffffu, ls1, 2);
        l0 = l0 * c0f + ls0;
        l1 = l1 * c1f + ls1;
        m0 = mn0; m1 = mn1;
#pragma unroll
        for (int nt = 0; nt < 8; nt++) {
            o[nt][0] *= c0f; o[nt][1] *= c0f;
            o[nt][2] *= c1f; o[nt][3] *= c1f;
        }

#pragma unroll
        for (int kk = 0; kk < 4; kk++) {
#pragma unroll
            for (int dt = 0; dt < 4; dt++) {
                uint32_t b0, b1, b2, b3;
                LDM_X4T(b0, b1, b2, b3, sV + bKV + kk * (16 * ASTRIDE * 2) + dt * 32);
                MMA_BF16(o[dt * 2],     pa[kk][0], pa[kk][1], pa[kk][2], pa[kk][3], b0, b1);
                MMA_BF16(o[dt * 2 + 1], pa[kk][0], pa[kk][1], pa[kk][2], pa[kk][3], b2, b3);
            }
        }
        __syncthreads();
    }

    const float inv0 = 1.f / l0, inv1 = 1.f / l1;
    const int colb = h * 64 + cql;
#pragma unroll
    for (int nt = 0; nt < 8; nt++) {
        int col = colb + nt * 8;
#pragma unroll
        for (int half = 0; half < 2; half++) {
            float inv = half ? inv1 : inv0;
            float v0 = o[nt][half * 2 + 0] * inv;
            float v1 = o[nt][half * 2 + 1] * inv;
            int row = qbase + w * 16 + r0 + half * 8;
            __half2 hp;
            hp.x = __float2half_rn(v0);
            hp.y = __float2half_rn(v1);
            *(__half2*)&outs[(size_t)(b * SS + row) * DM + col] = hp;
        }
    }
}

// ---------------- layernorm (input already residual-summed) ----------------
template <int SPLIT>
__global__ void __launch_bounds__(256)
ln_res_kernel(const float* __restrict__ a,
              const float* __restrict__ g, const float* __restrict__ bt,
              float* __restrict__ out, __half* __restrict__ outs)
{
    __shared__ float red[8];
    const int row = blockIdx.x;
    const int tid = threadIdx.x;
    const float* pa = a + (size_t)row * DM;

    float v[4];
    float sum = 0.f;
#pragma unroll
    for (int j = 0; j < 4; j++) {
        int c = tid + j * 256;
        v[j] = pa[c];
        sum += v[j];
    }
#pragma unroll
    for (int o = 16; o > 0; o >>= 1) sum += __shfl_xor_sync(0xffffffffu, sum, o);
    if ((tid & 31) == 0) red[tid >> 5] = sum;
    __syncthreads();
    float tot = 0.f;
#pragma unroll
    for (int ww = 0; ww < 8; ww++) tot += red[ww];
    const float mean = tot * (1.f / (float)DM);

    float sq = 0.f;
#pragma unroll
    for (int j = 0; j < 4; j++) { float dd = v[j] - mean; sq += dd * dd; }
    __syncthreads();
#pragma unroll
    for (int o = 16; o > 0; o >>= 1) sq += __shfl_xor_sync(0xffffffffu, sq, o);
    if ((tid & 31) == 0) red[tid >> 5] = sq;
    __syncthreads();
    float vtot = 0.f;
#pragma unroll
    for (int ww = 0; ww < 8; ww++) vtot += red[ww];
    const float inv = rsqrtf(vtot * (1.f / (float)DM) + 1e-5f);

#pragma unroll
    for (int j = 0; j < 4; j++) {
        int c = tid + j * 256;
        float o = (v[j] - mean) * inv * g[c] + bt[c];
        out[(size_t)row * DM + c] = o;
        if (SPLIT)
            outs[(size_t)row * DM + c] = __float2half_rn(o);
    }
}

// ---------------- host ----------------
extern "C" void kernel_launch(void* const* d_in, const int* in_sizes, int n_in,
                              void* d_out, int out_size)
{
    const float* x     = (const float*)d_in[0];
    const float* se    = (const float*)d_in[1];
    const float* qkv_w = (const float*)d_in[2];
    const float* qkv_b = (const float*)d_in[3];
    const float* out_w = (const float*)d_in[4];
    const float* out_b = (const float*)d_in[5];
    const float* rpb   = (const float*)d_in[6];
    const float* w1    = (const float*)d_in[7];
    const float* b1    = (const float*)d_in[8];
    const float* w2    = (const float*)d_in[9];
    const float* b2    = (const float*)d_in[10];
    const float* ln1g  = (const float*)d_in[11];
    const float* ln1b  = (const float*)d_in[12];
    const float* ln2g  = (const float*)d_in[13];
    const float* ln2b  = (const float*)d_in[14];
    const int*   ts    = (const int*)d_in[15];
    float* out = (float*)d_out;

    float *x0, *res1, *x1, *res2;
    __nv_bfloat16 *qkvh;
    __half *x0s, *attns, *x1s, *hs, *wqkvs, *wouts, *w1s, *w2s;
    cudaGetSymbolAddress((void**)&x0,   g_x0);
    cudaGetSymbolAddress((void**)&qkvh, g_qkvh);
    cudaGetSymbolAddress((void**)&res1, g_res1);
    cudaGetSymbolAddress((void**)&x1,   g_x1);
    cudaGetSymbolAddress((void**)&res2, g_res2);
    cudaGetSymbolAddress((void**)&x0s,   g_x0s);
    cudaGetSymbolAddress((void**)&attns, g_attns);
    cudaGetSymbolAddress((void**)&x1s,   g_x1s);
    cudaGetSymbolAddress((void**)&hs,    g_hs);
    cudaGetSymbolAddress((void**)&wqkvs, g_wqkvs);
    cudaGetSymbolAddress((void**)&wouts, g_wouts);
    cudaGetSymbolAddress((void**)&w1s,   g_w1s);
    cudaGetSymbolAddress((void**)&w2s,   g_w2s);

    cudaFuncSetAttribute(gemm_mma<0>, cudaFuncAttributeMaxDynamicSharedMemorySize, GSMEM);
    cudaFuncSetAttribute(gemm_mma<1>, cudaFuncAttributeMaxDynamicSharedMemorySize, GSMEM);
    cudaFuncSetAttribute(gemm_mma<2>, cudaFuncAttributeMaxDynamicSharedMemorySize, GSMEM);

    wconv_kernel<<<dim3(3 * DM / 32, DM / 32),  dim3(32, 8)>>>(qkv_w, wqkvs, DM, 3 * DM);
    wconv_kernel<<<dim3(DM / 32, DM / 32),      dim3(32, 8)>>>(out_w, wouts, DM, DM);
    wconv_kernel<<<dim3(DFF / 32, DM / 32),     dim3(32, 8)>>>(w1, w1s, DM, DFF);
    wconv_kernel<<<dim3(DM / 32, DFF / 32),     dim3(32, 8)>>>(w2, w2s, DFF, DM);

    add_step_kernel<<<(MTOK * DM) / 256, 256>>>(x, se, ts, x0, x0s);

    gemm_mma<2><<<dim3(3 * DM / 128, MTOK / 128), 256, GSMEM>>>(
        x0s, wqkvs, qkv_b, nullptr, nullptr, qkvh, 3 * DM, DM);

    attn_mma_kernel<<<dim3(SS / 64, NH, BB), 128>>>(qkvh, rpb, attns);

    // res1 = attn@Wo + b + x0
    gemm_mma<0><<<dim3(DM / 128, MTOK / 128), 256, GSMEM>>>(
        attns, wouts, out_b, x0, res1, nullptr, DM, DM);

    ln_res_kernel<1><<<MTOK, 256>>>(res1, ln1g, ln1b, x1, x1s);

    gemm_mma<1><<<dim3(DFF / 128, MTOK / 128), 256, GSMEM>>>(
        x1s, w1s, b1, nullptr, nullptr, hs, DFF, DM);

    // res2 = h@W2 + b + x1
    gemm_mma<0><<<dim3(DM / 128, MTOK / 128), 256, GSMEM>>>(
        hs, w2s, b2, x1, res2, nullptr, DM, DFF);

    ln_res_kernel<0><<<MTOK, 256>>>(res2, ln2g, ln2b, out, nullptr);
}

// round 12
// speedup vs baseline: 1.0926x; 1.0926x over previous
#include <cuda_runtime.h>
#include <cuda_bf16.h>
#include <cuda_fp16.h>
#include <math.h>
#include <stdint.h>

#define DM   1024
#define NH   16
#define DFF  4096
#define BB   8
#define SS   1024
#define MTOK (BB*SS)

// ---------------- scratch ----------------
__device__ float g_x0  [MTOK*DM];
__device__ __nv_bfloat16 g_qkvh[(size_t)MTOK*3*DM];
__device__ float g_res1[MTOK*DM];   // x0 + proj (pre-LN1)
__device__ float g_x1  [MTOK*DM];
__device__ float g_res2[MTOK*DM];   // x1 + ffn (pre-LN2)
__device__ __half g_x0s  [(size_t)MTOK*DM];
__device__ __half g_attns[(size_t)MTOK*DM];
__device__ __half g_x1s  [(size_t)MTOK*DM];
__device__ __half g_hs   [(size_t)MTOK*DFF];
__device__ __half g_wqkvs[(size_t)(3*DM)*DM];
__device__ __half g_wouts[(size_t)DM*DM];
__device__ __half g_w1s  [(size_t)DFF*DM];
__device__ __half g_w2s  [(size_t)DM*DFF];

// ---------------- asm helpers ----------------
__device__ __forceinline__ uint32_t smem_u32(const void* p) {
    uint32_t a;
    asm("{ .reg .u64 t; cvta.to.shared.u64 t, %1; cvt.u32.u64 %0, t; }" : "=r"(a) : "l"(p));
    return a;
}
#define CP_ASYNC16(saddr, gptr) \
    asm volatile("cp.async.cg.shared.global [%0], [%1], 16;" :: "r"(saddr), "l"(gptr))
#define CP_COMMIT() asm volatile("cp.async.commit_group;" ::: "memory")
#define CP_WAIT1()  asm volatile("cp.async.wait_group 1;" ::: "memory")
#define CP_WAIT0()  asm volatile("cp.async.wait_group 0;" ::: "memory")

#define LDM_X4(r0, r1, r2, r3, a) \
    asm volatile("ldmatrix.sync.aligned.m8n8.x4.shared.b16 {%0,%1,%2,%3}, [%4];" \
                 : "=r"(r0), "=r"(r1), "=r"(r2), "=r"(r3) : "r"(a))
#define LDM_X4T(r0, r1, r2, r3, a) \
    asm volatile("ldmatrix.sync.aligned.m8n8.x4.trans.shared.b16 {%0,%1,%2,%3}, [%4];" \
                 : "=r"(r0), "=r"(r1), "=r"(r2), "=r"(r3) : "r"(a))
#define LDM_X2(r0, r1, a) \
    asm volatile("ldmatrix.sync.aligned.m8n8.x2.shared.b16 {%0,%1}, [%2];" \
                 : "=r"(r0), "=r"(r1) : "r"(a))

#define MMA_F16(d, a0, a1, a2, a3, b0, b1) \
    asm volatile("mma.sync.aligned.m16n8k16.row.col.f32.f16.f16.f32 " \
                 "{%0,%1,%2,%3}, {%4,%5,%6,%7}, {%8,%9}, {%0,%1,%2,%3};" \
                 : "+f"((d)[0]), "+f"((d)[1]), "+f"((d)[2]), "+f"((d)[3]) \
                 : "r"(a0), "r"(a1), "r"(a2), "r"(a3), "r"(b0), "r"(b1))
#define MMA_BF16(d, a0, a1, a2, a3, b0, b1) \
    asm volatile("mma.sync.aligned.m16n8k16.row.col.f32.bf16.bf16.f32 " \
                 "{%0,%1,%2,%3}, {%4,%5,%6,%7}, {%8,%9}, {%0,%1,%2,%3};" \
                 : "+f"((d)[0]), "+f"((d)[1]), "+f"((d)[2]), "+f"((d)[3]) \
                 : "r"(a0), "r"(a1), "r"(a2), "r"(a3), "r"(b0), "r"(b1))

__device__ __forceinline__ float gelu_exact(float v) {
    return 0.5f * v * (1.0f + erff(v * 0.70710678118654752f));
}
__device__ __forceinline__ uint32_t pack_bf162(float lo, float hi) {
    __nv_bfloat162 t = __floats2bfloat162_rn(lo, hi);
    return *(uint32_t*)&t;
}

// ---------------- GEMM via mma.sync (fp16, f32 accum) --------------------
// CTA 128x128, BK=64, 3-stage cp.async pipeline, 8 warps of 64x32.
// ACT=0: f32 out = acc + bias + res. ACT=1: half gelu out. ACT=2: bf16 out
// (Q cols pre-scaled 0.125). Mainloop identical to round-10 (proven).
#define ROWB    144
#define STG_B   (128 * ROWB)
#define NSTAGE  3
#define GSMEM   (NSTAGE * STG_B * 2)

template <int ACT>
__global__ void __launch_bounds__(256, 2)
gemm_mma(const __half* __restrict__ A, const __half* __restrict__ B,
         const float* __restrict__ bias, const float* __restrict__ res,
         float* __restrict__ Cf, void* __restrict__ Cx, int Ndim, int Kp)
{
    extern __shared__ __align__(128) char smem[];
    const uint32_t sA = smem_u32(smem);
    const uint32_t sB = sA + NSTAGE * STG_B;

    const int tid  = threadIdx.x;
    const int lane = tid & 31;
    const int wid  = tid >> 5;
    const int wm   = wid & 1;
    const int wn   = wid >> 1;
    const int row0 = blockIdx.y * 128;
    const int n0   = blockIdx.x * 128;

    const uint32_t aLd = sA + (wm * 64 + (lane & 15)) * ROWB + (lane >> 4) * 16;
    const uint32_t bLd = sB + (wn * 32 + (lane & 7)) * ROWB + ((lane >> 3) & 1) * 16;

    float d[4][4][4];
#pragma unroll
    for (int i = 0; i < 4; i++)
#pragma unroll
        for (int j = 0; j < 4; j++)
#pragma unroll
            for (int c = 0; c < 4; c++) d[i][j][c] = 0.f;

    const int kTiles = Kp >> 6;

    auto load_stage = [&](int kt, int s) {
        const int k0 = kt * 64;
        const uint32_t dA = sA + s * STG_B;
        const uint32_t dB = sB + s * STG_B;
#pragma unroll
        for (int j = 0; j < 4; j++) {
            int id = tid + 256 * j;
            int r = id >> 3;
            int cb = (id & 7) * 16;
            CP_ASYNC16(dA + r * ROWB + cb,
                       (const char*)(A + (size_t)(row0 + r) * Kp + k0) + cb);
            CP_ASYNC16(dB + r * ROWB + cb,
                       (const char*)(B + (size_t)(n0 + r) * Kp + k0) + cb);
        }
        CP_COMMIT();
    };

    load_stage(0, 0);
    load_stage(1, 1);

    for (int kt = 0; kt < kTiles; kt++) {
        CP_WAIT1();
        __syncthreads();

        if (kt + 2 < kTiles) {
            load_stage(kt + 2, (kt + 2) % NSTAGE);
        } else {
            CP_COMMIT();
        }

        const int st = kt % NSTAGE;
        const uint32_t aS = aLd + st * STG_B;
        const uint32_t bS = bLd + st * STG_B;
#pragma unroll
        for (int k16 = 0; k16 < 4; k16++) {
            uint32_t a[4][4], b[4][2];
#pragma unroll
            for (int mt = 0; mt < 4; mt++)
                LDM_X4(a[mt][0], a[mt][1], a[mt][2], a[mt][3],
                       aS + mt * (16 * ROWB) + k16 * 32);
#pragma unroll
            for (int nt = 0; nt < 4; nt++)
                LDM_X2(b[nt][0], b[nt][1], bS + nt * (8 * ROWB) + k16 * 32);
#pragma unroll
            for (int mt = 0; mt < 4; mt++)
#pragma unroll
                for (int nt = 0; nt < 4; nt++)
                    MMA_F16(d[mt][nt], a[mt][0], a[mt][1], a[mt][2], a[mt][3],
                            b[nt][0], b[nt][1]);
        }
        __syncthreads();
    }
    CP_WAIT0();

#pragma unroll
    for (int mt = 0; mt < 4; mt++) {
#pragma unroll
        for (int half = 0; half < 2; half++) {
            const int row = row0 + wm * 64 + mt * 16 + (lane >> 2) + half * 8;
#pragma unroll
            for (int nt = 0; nt < 4; nt++) {
                const int col = n0 + wn * 32 + nt * 8 + (lane & 3) * 2;
                float v0 = d[mt][nt][half * 2 + 0] + bias[col];
                float v1 = d[mt][nt][half * 2 + 1] + bias[col + 1];
                if (ACT == 0) {
                    float2 rr = *(const float2*)&res[(size_t)row * Ndim + col];
                    float2 o; o.x = v0 + rr.x; o.y = v1 + rr.y;
                    *(float2*)&Cf[(size_t)row * Ndim + col] = o;
                } else if (ACT == 1) {
                    v0 = gelu_exact(v0);
                    v1 = gelu_exact(v1);
                    __half2 hp;
                    hp.x = __float2half_rn(v0);
                    hp.y = __float2half_rn(v1);
                    *(__half2*)&((__half*)Cx)[(size_t)row * Ndim + col] = hp;
                } else {
                    const float sc = (col < 1024) ? 0.125f : 1.0f;
                    __nv_bfloat162 hp = __floats2bfloat162_rn(v0 * sc, v1 * sc);
                    *(__nv_bfloat162*)&((__nv_bfloat16*)Cx)[(size_t)row * Ndim + col] = hp;
                }
            }
        }
    }
}

// -------- weight transpose to fp16: W[K,N] -> Wt[N,K] --------
__global__ void wconv_kernel(const float* __restrict__ W, __half* __restrict__ Wt,
                             int K, int N)
{
    __shared__ float t[32][33];
    const int n0 = blockIdx.x * 32, k0 = blockIdx.y * 32;
#pragma unroll
    for (int i = threadIdx.y; i < 32; i += 8)
        t[i][threadIdx.x] = W[(size_t)(k0 + i) * N + n0 + threadIdx.x];
    __syncthreads();
#pragma unroll
    for (int i = threadIdx.y; i < 32; i += 8) {
        int n = n0 + i, k = k0 + threadIdx.x;
        Wt[(size_t)n * K + k] = __float2half_rn(t[threadIdx.x][i]);
    }
}

// -------- add step embed; fp16 copy --------
__global__ void add_step_kernel(const float* __restrict__ x, const float* __restrict__ se,
                                const int* __restrict__ ts, float* __restrict__ x0,
                                __half* __restrict__ xs)
{
    int i = blockIdx.x * blockDim.x + threadIdx.x;
    int step = ts[0];
    if (step > 15) step = 15;
    if (step < 0) step += 16;
    int k = i & (DM - 1);
    float v = x[i] + se[step * DM + k];
    x0[i] = v;
    xs[i] = __float2half_rn(v);
}

// ---------------- flash attention on tensor cores (bf16 in, bf16 mma) -----------
#define ASTRIDE 72
#define KVB (64 * ASTRIDE * 2)
__global__ void __launch_bounds__(128)
attn_mma_kernel(const __nv_bfloat16* __restrict__ qkvh, const float* __restrict__ rpb,
                __half* __restrict__ outs)
{
    __shared__ __nv_bfloat16 Qs[64 * ASTRIDE];
    __shared__ __nv_bfloat16 Kst[2][64 * ASTRIDE];
    __shared__ __nv_bfloat16 Vst[2][64 * ASTRIDE];
    __shared__ float rb[128];

    const int tid = threadIdx.x;
    const int lane = tid & 31;
    const int w = tid >> 5;
    const int qt = blockIdx.x, h = blockIdx.y, b = blockIdx.z;
    const int qbase = qt * 64;

    if (tid < 127) rb[tid] = rpb[tid];

    {
        int r = tid >> 1;
        int c0 = (tid & 1) * 32;
        const uint4* src = (const uint4*)(qkvh + ((size_t)(b * SS + qbase + r)) * 3072 + h * 64 + c0);
        uint4* dst = (uint4*)&Qs[r * ASTRIDE + c0];
#pragma unroll
        for (int j = 0; j < 4; j++) dst[j] = src[j];
    }

    const uint32_t sQ = smem_u32(Qs);
    const uint32_t sK0 = smem_u32(Kst);
    const uint32_t sV0 = smem_u32(Vst);
    const uint32_t aQ = sQ + (w * 16 + (lane & 15)) * (ASTRIDE * 2) + (lane >> 4) * 16;
    const uint32_t bKV = (((lane >> 3) & 1) * 8 + (lane & 7)) * (ASTRIDE * 2) + (lane >> 4) * 16;

    auto load_kv = [&](int kt, int st) {
#pragma unroll
        for (int j = 0; j < 4; j++) {
            int id = tid + 128 * j;
            int r = id >> 3;
            int cb = (id & 7) * 8;
            const char* gsrc = (const char*)(qkvh + ((size_t)(b * SS + kt * 64 + r)) * 3072 + h * 64 + cb);
            CP_ASYNC16(sK0 + st * KVB + r * (ASTRIDE * 2) + cb * 2, gsrc + 2048);
            CP_ASYNC16(sV0 + st * KVB + r * (ASTRIDE * 2) + cb * 2, gsrc + 4096);
        }
        CP_COMMIT();
    };

    load_kv(0, 0);

    float m0 = -1e30f, m1 = -1e30f, l0 = 0.f, l1 = 0.f;
    float o[8][4];
#pragma unroll
    for (int nt = 0; nt < 8; nt++)
#pragma unroll
        for (int j = 0; j < 4; j++) o[nt][j] = 0.f;

    const int r0 = lane >> 2;
    const int cql = (lane & 3) * 2;
    const int qg0 = qbase + w * 16 + r0;

    for (int kt = 0; kt < 16; kt++) {
        const int st = kt & 1;
        if (kt + 1 < 16) {
            load_kv(kt + 1, st ^ 1);
            CP_WAIT1();
        } else {
            CP_WAIT0();
        }
        __syncthreads();

        const uint32_t sK = sK0 + st * KVB;
        const uint32_t sV = sV0 + st * KVB;

        float s[8][4];
#pragma unroll
        for (int nt = 0; nt < 8; nt++)
#pragma unroll
            for (int j = 0; j < 4; j++) s[nt][j] = 0.f;
#pragma unroll
        for (int k16 = 0; k16 < 4; k16++) {
            uint32_t a0, a1, a2, a3;
            LDM_X4(a0, a1, a2, a3, aQ + k16 * 32);
#pragma unroll
            for (int np = 0; np < 4; np++) {
                uint32_t b0, b1, b2, b3;
                LDM_X4(b0, b1, b2, b3, sK + bKV + np * (16 * ASTRIDE * 2) + k16 * 32);
                MMA_BF16(s[np * 2],     a0, a1, a2, a3, b0, b2);
                MMA_BF16(s[np * 2 + 1], a0, a1, a2, a3, b1, b3);
            }
        }

        const int kb = kt * 64 + cql;
        float mt0 = -1e30f, mt1 = -1e30f;
#pragma unroll
        for (int nt = 0; nt < 8; nt++) {
            int kg = kb + nt * 8;
            int i00 = min(max(qg0 - kg + 63, 0), 126);
            int i01 = min(max(qg0 - kg + 62, 0), 126);
            int i10 = min(max(qg0 - kg + 71, 0), 126);
            int i11 = min(max(qg0 - kg + 70, 0), 126);
            s[nt][0] += rb[i00]; s[nt][1] += rb[i01];
            s[nt][2] += rb[i10]; s[nt][3] += rb[i11];
            mt0 = fmaxf(mt0, fmaxf(s[nt][0], s[nt][1]));
            mt1 = fmaxf(mt1, fmaxf(s[nt][2], s[nt][3]));
        }
        mt0 = fmaxf(mt0, __shfl_xor_sync(0xffffffffu, mt0, 1));
        mt0 = fmaxf(mt0, __shfl_xor_sync(0xffffffffu, mt0, 2));
        mt1 = fmaxf(mt1, __shfl_xor_sync(0xffffffffu, mt1, 1));
        mt1 = fmaxf(mt1, __shfl_xor_sync(0xffffffffu, mt1, 2));

        float mn0 = fmaxf(m0, mt0), mn1 = fmaxf(m1, mt1);
        float c0f = __expf(m0 - mn0), c1f = __expf(m1 - mn1);
        float ls0 = 0.f, ls1 = 0.f;
        uint32_t pa[4][4];
#pragma unroll
        for (int nt = 0; nt < 8; nt++) {
            float p0 = __expf(s[nt][0] - mn0);
            float p1 = __expf(s[nt][1] - mn0);
            float p2 = __expf(s[nt][2] - mn1);
            float p3 = __expf(s[nt][3] - mn1);
            ls0 += p0 + p1; ls1 += p2 + p3;
            uint32_t lo = pack_bf162(p0, p1);
            uint32_t hi = pack_bf162(p2, p3);
            if ((nt & 1) == 0) { pa[nt >> 1][0] = lo; pa[nt >> 1][1] = hi; }
            else               { pa[nt >> 1][2] = lo; pa[nt >> 1][3] = hi; }
        }
        ls0 += __shfl_xor_sync(0xffffffffu, ls0, 1);
        ls0 += __shfl_xor_sync(0xffffffffu, ls0, 2);
        ls1 += __shfl_xor_sync(0xffffffffu, ls1, 1);
        ls1 += __shfl_xor_sync(0xffffffffu, ls1, 2);
        l0 = l0 * c0f + ls0;
        l1 = l1 * c1f + ls1;
        m0 = mn0; m1 = mn1;
#pragma unroll
        for (int nt = 0; nt < 8; nt++) {
            o[nt][0] *= c0f; o[nt][1] *= c0f;
            o[nt][2] *= c1f; o[nt][3] *= c1f;
        }

#pragma unroll
        for (int kk = 0; kk < 4; kk++) {
#pragma unroll
            for (int dt = 0; dt < 4; dt++) {
                uint32_t b0, b1, b2, b3;
                LDM_X4T(b0, b1, b2, b3, sV + bKV + kk * (16 * ASTRIDE * 2) + dt * 32);
                MMA_BF16(o[dt * 2],     pa[kk][0], pa[kk][1], pa[kk][2], pa[kk][3], b0, b1);
                MMA_BF16(o[dt * 2 + 1], pa[kk][0], pa[kk][1], pa[kk][2], pa[kk][3], b2, b3);
            }
        }
        __syncthreads();
    }

    const float inv0 = 1.f / l0, inv1 = 1.f / l1;
    const int colb = h * 64 + cql;
#pragma unroll
    for (int nt = 0; nt < 8; nt++) {
        int col = colb + nt * 8;
#pragma unroll
        for (int half = 0; half < 2; half++) {
            float inv = half ? inv1 : inv0;
            float v0 = o[nt][half * 2 + 0] * inv;
            float v1 = o[nt][half * 2 + 1] * inv;
            int row = qbase + w * 16 + r0 + half * 8;
            __half2 hp;
            hp.x = __float2half_rn(v0);
            hp.y = __float2half_rn(v1);
            *(__half2*)&outs[(size_t)(b * SS + row) * DM + col] = hp;
        }
    }
}

// ---------------- layernorm (input already residual-summed) ----------------
template <int SPLIT>
__global__ void __launch_bounds__(256)
ln_res_kernel(const float* __restrict__ a,
              const float* __restrict__ g, const float* __restrict__ bt,
              float* __restrict__ out, __half* __restrict__ outs)
{
    __shared__ float red[8];
    const int row = blockIdx.x;
    const int tid = threadIdx.x;
    const float* pa = a + (size_t)row * DM;

    float v[4];
    float sum = 0.f;
#pragma unroll
    for (int j = 0; j < 4; j++) {
        int c = tid + j * 256;
        v[j] = pa[c];
        sum += v[j];
    }
#pragma unroll
    for (int o = 16; o > 0; o >>= 1) sum += __shfl_xor_sync(0xffffffffu, sum, o);
    if ((tid & 31) == 0) red[tid >> 5] = sum;
    __syncthreads();
    float tot = 0.f;
#pragma unroll
    for (int ww = 0; ww < 8; ww++) tot += red[ww];
    const float mean = tot * (1.f / (float)DM);

    float sq = 0.f;
#pragma unroll
    for (int j = 0; j < 4; j++) { float dd = v[j] - mean; sq += dd * dd; }
    __syncthreads();
#pragma unroll
    for (int o = 16; o > 0; o >>= 1) sq += __shfl_xor_sync(0xffffffffu, sq, o);
    if ((tid & 31) == 0) red[tid >> 5] = sq;
    __syncthreads();
    float vtot = 0.f;
#pragma unroll
    for (int ww = 0; ww < 8; ww++) vtot += red[ww];
    const float inv = rsqrtf(vtot * (1.f / (float)DM) + 1e-5f);

#pragma unroll
    for (int j = 0; j < 4; j++) {
        int c = tid + j * 256;
        float o = (v[j] - mean) * inv * g[c] + bt[c];
        out[(size_t)row * DM + c] = o;
        if (SPLIT)
            outs[(size_t)row * DM + c] = __float2half_rn(o);
    }
}

// ---------------- host ----------------
extern "C" void kernel_launch(void* const* d_in, const int* in_sizes, int n_in,
                              void* d_out, int out_size)
{
    const float* x     = (const float*)d_in[0];
    const float* se    = (const float*)d_in[1];
    const float* qkv_w = (const float*)d_in[2];
    const float* qkv_b = (const float*)d_in[3];
    const float* out_w = (const float*)d_in[4];
    const float* out_b = (const float*)d_in[5];
    const float* rpb   = (const float*)d_in[6];
    const float* w1    = (const float*)d_in[7];
    const float* b1    = (const float*)d_in[8];
    const float* w2    = (const float*)d_in[9];
    const float* b2    = (const float*)d_in[10];
    const float* ln1g  = (const float*)d_in[11];
    const float* ln1b  = (const float*)d_in[12];
    const float* ln2g  = (const float*)d_in[13];
    const float* ln2b  = (const float*)d_in[14];
    const int*   ts    = (const int*)d_in[15];
    float* out = (float*)d_out;

    float *x0, *res1, *x1, *res2;
    __nv_bfloat16 *qkvh;
    __half *x0s, *attns, *x1s, *hs, *wqkvs, *wouts, *w1s, *w2s;
    cudaGetSymbolAddress((void**)&x0,   g_x0);
    cudaGetSymbolAddress((void**)&qkvh, g_qkvh);
    cudaGetSymbolAddress((void**)&res1, g_res1);
    cudaGetSymbolAddress((void**)&x1,   g_x1);
    cudaGetSymbolAddress((void**)&res2, g_res2);
    cudaGetSymbolAddress((void**)&x0s,   g_x0s);
    cudaGetSymbolAddress((void**)&attns, g_attns);
    cudaGetSymbolAddress((void**)&x1s,   g_x1s);
    cudaGetSymbolAddress((void**)&hs,    g_hs);
    cudaGetSymbolAddress((void**)&wqkvs, g_wqkvs);
    cudaGetSymbolAddress((void**)&wouts, g_wouts);
    cudaGetSymbolAddress((void**)&w1s,   g_w1s);
    cudaGetSymbolAddress((void**)&w2s,   g_w2s);

    cudaFuncSetAttribute(gemm_mma<0>, cudaFuncAttributeMaxDynamicSharedMemorySize, GSMEM);
    cudaFuncSetAttribute(gemm_mma<1>, cudaFuncAttributeMaxDynamicSharedMemorySize, GSMEM);
    cudaFuncSetAttribute(gemm_mma<2>, cudaFuncAttributeMaxDynamicSharedMemorySize, GSMEM);

    wconv_kernel<<<dim3(3 * DM / 32, DM / 32),  dim3(32, 8)>>>(qkv_w, wqkvs, DM, 3 * DM);
    wconv_kernel<<<dim3(DM / 32, DM / 32),      dim3(32, 8)>>>(out_w, wouts, DM, DM);
    wconv_kernel<<<dim3(DFF / 32, DM / 32),     dim3(32, 8)>>>(w1, w1s, DM, DFF);
    wconv_kernel<<<dim3(DM / 32, DFF / 32),     dim3(32, 8)>>>(w2, w2s, DFF, DM);

    add_step_kernel<<<(MTOK * DM) / 256, 256>>>(x, se, ts, x0, x0s);

    gemm_mma<2><<<dim3(3 * DM / 128, MTOK / 128), 256, GSMEM>>>(
        x0s, wqkvs, qkv_b, nullptr, nullptr, qkvh, 3 * DM, DM);

    attn_mma_kernel<<<dim3(SS / 64, NH, BB), 128>>>(qkvh, rpb, attns);

    // res1 = attn@Wo + b + x0
    gemm_mma<0><<<dim3(DM / 128, MTOK / 128), 256, GSMEM>>>(
        attns, wouts, out_b, x0, res1, nullptr, DM, DM);

    ln_res_kernel<1><<<MTOK, 256>>>(res1, ln1g, ln1b, x1, x1s);

    gemm_mma<1><<<dim3(DFF / 128, MTOK / 128), 256, GSMEM>>>(
        x1s, w1s, b1, nullptr, nullptr, hs, DFF, DM);

    // res2 = h@W2 + b + x1
    gemm_mma<0><<<dim3(DM / 128, MTOK / 128), 256, GSMEM>>>(
        hs, w2s, b2, x1, res2, nullptr, DM, DFF);

    ln_res_kernel<0><<<MTOK, 256>>>(res2, ln2g, ln2b, out, nullptr);
}

// round 13
// speedup vs baseline: 1.1355x; 1.0393x over previous
#include <cuda_runtime.h>
#include <cuda_bf16.h>
#include <cuda_fp16.h>
#include <math.h>
#include <stdint.h>

#define DM   1024
#define NH   16
#define DFF  4096
#define BB   8
#define SS   1024
#define MTOK (BB*SS)

// ---------------- scratch ----------------
__device__ float g_x0  [MTOK*DM];
__device__ __nv_bfloat16 g_qkvh[(size_t)MTOK*3*DM];
__device__ float g_proj[MTOK*DM];
__device__ float g_x1  [MTOK*DM];
__device__ float g_ffn [MTOK*DM];
__device__ __half g_x0s  [(size_t)MTOK*DM];
__device__ __half g_attns[(size_t)MTOK*DM];
__device__ __half g_x1s  [(size_t)MTOK*DM];
__device__ __half g_hs   [(size_t)MTOK*DFF];
__device__ __half g_wqkvs[(size_t)(3*DM)*DM];
__device__ __half g_wouts[(size_t)DM*DM];
__device__ __half g_w1s  [(size_t)DFF*DM];
__device__ __half g_w2s  [(size_t)DM*DFF];

// ---------------- asm helpers ----------------
__device__ __forceinline__ uint32_t smem_u32(const void* p) {
    uint32_t a;
    asm("{ .reg .u64 t; cvta.to.shared.u64 t, %1; cvt.u32.u64 %0, t; }" : "=r"(a) : "l"(p));
    return a;
}
#define CP_ASYNC16(saddr, gptr) \
    asm volatile("cp.async.cg.shared.global [%0], [%1], 16;" :: "r"(saddr), "l"(gptr))
#define CP_COMMIT() asm volatile("cp.async.commit_group;" ::: "memory")
#define CP_WAIT1()  asm volatile("cp.async.wait_group 1;" ::: "memory")
#define CP_WAIT0()  asm volatile("cp.async.wait_group 0;" ::: "memory")

#define LDM_X4(r0, r1, r2, r3, a) \
    asm volatile("ldmatrix.sync.aligned.m8n8.x4.shared.b16 {%0,%1,%2,%3}, [%4];" \
                 : "=r"(r0), "=r"(r1), "=r"(r2), "=r"(r3) : "r"(a))
#define LDM_X4T(r0, r1, r2, r3, a) \
    asm volatile("ldmatrix.sync.aligned.m8n8.x4.trans.shared.b16 {%0,%1,%2,%3}, [%4];" \
                 : "=r"(r0), "=r"(r1), "=r"(r2), "=r"(r3) : "r"(a))
#define LDM_X2(r0, r1, a) \
    asm volatile("ldmatrix.sync.aligned.m8n8.x2.shared.b16 {%0,%1}, [%2];" \
                 : "=r"(r0), "=r"(r1) : "r"(a))

#define MMA_F16(d, a0, a1, a2, a3, b0, b1) \
    asm volatile("mma.sync.aligned.m16n8k16.row.col.f32.f16.f16.f32 " \
                 "{%0,%1,%2,%3}, {%4,%5,%6,%7}, {%8,%9}, {%0,%1,%2,%3};" \
                 : "+f"((d)[0]), "+f"((d)[1]), "+f"((d)[2]), "+f"((d)[3]) \
                 : "r"(a0), "r"(a1), "r"(a2), "r"(a3), "r"(b0), "r"(b1))
#define MMA_BF16(d, a0, a1, a2, a3, b0, b1) \
    asm volatile("mma.sync.aligned.m16n8k16.row.col.f32.bf16.bf16.f32 " \
                 "{%0,%1,%2,%3}, {%4,%5,%6,%7}, {%8,%9}, {%0,%1,%2,%3};" \
                 : "+f"((d)[0]), "+f"((d)[1]), "+f"((d)[2]), "+f"((d)[3]) \
                 : "r"(a0), "r"(a1), "r"(a2), "r"(a3), "r"(b0), "r"(b1))

__device__ __forceinline__ float gelu_exact(float v) {
    return 0.5f * v * (1.0f + erff(v * 0.70710678118654752f));
}
__device__ __forceinline__ uint32_t pack_bf162(float lo, float hi) {
    __nv_bfloat162 t = __floats2bfloat162_rn(lo, hi);
    return *(uint32_t*)&t;
}

// ---------------- GEMM via mma.sync (fp16, f32 accum) --------------------
// CTA 128x128, BK=64, 3-stage cp.async pipeline, 8 warps of 64x32 (round-10 proven).
#define ROWB    144
#define STG_B   (128 * ROWB)
#define NSTAGE  3
#define GSMEM   (NSTAGE * STG_B * 2)

template <int ACT>
__global__ void __launch_bounds__(256, 2)
gemm_mma(const __half* __restrict__ A, const __half* __restrict__ B,
         const float* __restrict__ bias, float* __restrict__ Cf,
         void* __restrict__ Cx, int Ndim, int Kp)
{
    extern __shared__ __align__(128) char smem[];
    const uint32_t sA = smem_u32(smem);
    const uint32_t sB = sA + NSTAGE * STG_B;

    const int tid  = threadIdx.x;
    const int lane = tid & 31;
    const int wid  = tid >> 5;
    const int wm   = wid & 1;
    const int wn   = wid >> 1;
    const int row0 = blockIdx.y * 128;
    const int n0   = blockIdx.x * 128;

    const uint32_t aLd = sA + (wm * 64 + (lane & 15)) * ROWB + (lane >> 4) * 16;
    const uint32_t bLd = sB + (wn * 32 + (lane & 7)) * ROWB + ((lane >> 3) & 1) * 16;

    float d[4][4][4];
#pragma unroll
    for (int i = 0; i < 4; i++)
#pragma unroll
        for (int j = 0; j < 4; j++)
#pragma unroll
            for (int c = 0; c < 4; c++) d[i][j][c] = 0.f;

    const int kTiles = Kp >> 6;

    auto load_stage = [&](int kt, int s) {
        const int k0 = kt * 64;
        const uint32_t dA = sA + s * STG_B;
        const uint32_t dB = sB + s * STG_B;
#pragma unroll
        for (int j = 0; j < 4; j++) {
            int id = tid + 256 * j;
            int r = id >> 3;
            int cb = (id & 7) * 16;
            CP_ASYNC16(dA + r * ROWB + cb,
                       (const char*)(A + (size_t)(row0 + r) * Kp + k0) + cb);
            CP_ASYNC16(dB + r * ROWB + cb,
                       (const char*)(B + (size_t)(n0 + r) * Kp + k0) + cb);
        }
        CP_COMMIT();
    };

    load_stage(0, 0);
    load_stage(1, 1);

    for (int kt = 0; kt < kTiles; kt++) {
        CP_WAIT1();
        __syncthreads();

        if (kt + 2 < kTiles) {
            load_stage(kt + 2, (kt + 2) % NSTAGE);
        } else {
            CP_COMMIT();
        }

        const int st = kt % NSTAGE;
        const uint32_t aS = aLd + st * STG_B;
        const uint32_t bS = bLd + st * STG_B;
#pragma unroll
        for (int k16 = 0; k16 < 4; k16++) {
            uint32_t a[4][4], b[4][2];
#pragma unroll
            for (int mt = 0; mt < 4; mt++)
                LDM_X4(a[mt][0], a[mt][1], a[mt][2], a[mt][3],
                       aS + mt * (16 * ROWB) + k16 * 32);
#pragma unroll
            for (int nt = 0; nt < 4; nt++)
                LDM_X2(b[nt][0], b[nt][1], bS + nt * (8 * ROWB) + k16 * 32);
#pragma unroll
            for (int mt = 0; mt < 4; mt++)
#pragma unroll
                for (int nt = 0; nt < 4; nt++)
                    MMA_F16(d[mt][nt], a[mt][0], a[mt][1], a[mt][2], a[mt][3],
                            b[nt][0], b[nt][1]);
        }
        __syncthreads();
    }
    CP_WAIT0();

#pragma unroll
    for (int mt = 0; mt < 4; mt++) {
#pragma unroll
        for (int half = 0; half < 2; half++) {
            const int row = row0 + wm * 64 + mt * 16 + (lane >> 2) + half * 8;
#pragma unroll
            for (int nt = 0; nt < 4; nt++) {
                const int col = n0 + wn * 32 + nt * 8 + (lane & 3) * 2;
                float v0 = d[mt][nt][half * 2 + 0] + bias[col];
                float v1 = d[mt][nt][half * 2 + 1] + bias[col + 1];
                if (ACT == 0) {
                    float2 o; o.x = v0; o.y = v1;
                    *(float2*)&Cf[(size_t)row * Ndim + col] = o;
                } else if (ACT == 1) {
                    v0 = gelu_exact(v0);
                    v1 = gelu_exact(v1);
                    __half2 hp;
                    hp.x = __float2half_rn(v0);
                    hp.y = __float2half_rn(v1);
                    *(__half2*)&((__half*)Cx)[(size_t)row * Ndim + col] = hp;
                } else {
                    const float sc = (col < 1024) ? 0.125f : 1.0f;
                    __nv_bfloat162 hp = __floats2bfloat162_rn(v0 * sc, v1 * sc);
                    *(__nv_bfloat162*)&((__nv_bfloat16*)Cx)[(size_t)row * Ndim + col] = hp;
                }
            }
        }
    }
}

// ---------------- fused prep: add_step + all 4 weight transposes -----------------
// grid layout: [0,8192) add_step (vec4); then wconv tiles:
//   [8192, 11264)  qkv_w  (K=1024, N=3072)  96 x 32
//   [11264,12288)  out_w  (K=1024, N=1024)  32 x 32
//   [12288,16384)  w1     (K=1024, N=4096) 128 x 32
//   [16384,20480)  w2     (K=4096, N=1024)  32 x 128
#define PREP_BLOCKS 20480
__global__ void __launch_bounds__(256)
prep_kernel(const float* __restrict__ x, const float* __restrict__ se,
            const int* __restrict__ ts, float* __restrict__ x0, __half* __restrict__ xs,
            const float* __restrict__ qkv_w, const float* __restrict__ out_w,
            const float* __restrict__ w1, const float* __restrict__ w2,
            __half* __restrict__ wqkvs, __half* __restrict__ wouts,
            __half* __restrict__ w1s, __half* __restrict__ w2s)
{
    int b = blockIdx.x;
    const int tid = threadIdx.x;

    if (b < 8192) {
        // add_step: 1024 elems per block, 4 per thread
        int i = b * 1024 + tid * 4;
        int step = ts[0];
        if (step > 15) step = 15;
        if (step < 0) step += 16;
        int k = i & (DM - 1);
        float4 xv = *(const float4*)&x[i];
        float4 sv = *(const float4*)&se[step * DM + k];
        float4 v;
        v.x = xv.x + sv.x; v.y = xv.y + sv.y;
        v.z = xv.z + sv.z; v.w = xv.w + sv.w;
        *(float4*)&x0[i] = v;
        __half2 h0; h0.x = __float2half_rn(v.x); h0.y = __float2half_rn(v.y);
        __half2 h1; h1.x = __float2half_rn(v.z); h1.y = __float2half_rn(v.w);
        *(__half2*)&xs[i]     = h0;
        *(__half2*)&xs[i + 2] = h1;
        return;
    }
    b -= 8192;

    const float* W; __half* Wt; int K, N, bx, by;
    if (b < 3072)        { W = qkv_w; Wt = wqkvs; K = DM;  N = 3 * DM; bx = b % 96;  by = b / 96; }
    else if (b < 4096)   { b -= 3072; W = out_w; Wt = wouts; K = DM;  N = DM;  bx = b % 32;  by = b / 32; }
    else if (b < 8192)   { b -= 4096; W = w1;    Wt = w1s;   K = DM;  N = DFF; bx = b % 128; by = b / 128; }
    else                 { b -= 8192; W = w2;    Wt = w2s;   K = DFF; N = DM;  bx = b % 32;  by = b / 32; }

    __shared__ float t[32][33];
    const int tx = tid & 31;
    const int ty = tid >> 5;
    const int n0 = bx * 32, k0 = by * 32;
#pragma unroll
    for (int i = ty; i < 32; i += 8)
        t[i][tx] = W[(size_t)(k0 + i) * N + n0 + tx];
    __syncthreads();
#pragma unroll
    for (int i = ty; i < 32; i += 8)
        Wt[(size_t)(n0 + i) * K + k0 + tx] = __float2half_rn(t[tx][i]);
}

// ---------------- flash attention on tensor cores (bf16 in, bf16 mma) -----------
#define ASTRIDE 72
#define KVB (64 * ASTRIDE * 2)
__global__ void __launch_bounds__(128)
attn_mma_kernel(const __nv_bfloat16* __restrict__ qkvh, const float* __restrict__ rpb,
                __half* __restrict__ outs)
{
    __shared__ __nv_bfloat16 Qs[64 * ASTRIDE];
    __shared__ __nv_bfloat16 Kst[2][64 * ASTRIDE];
    __shared__ __nv_bfloat16 Vst[2][64 * ASTRIDE];
    __shared__ float rb[128];

    const int tid = threadIdx.x;
    const int lane = tid & 31;
    const int w = tid >> 5;
    const int qt = blockIdx.x, h = blockIdx.y, b = blockIdx.z;
    const int qbase = qt * 64;

    if (tid < 127) rb[tid] = rpb[tid];

    {
        int r = tid >> 1;
        int c0 = (tid & 1) * 32;
        const uint4* src = (const uint4*)(qkvh + ((size_t)(b * SS + qbase + r)) * 3072 + h * 64 + c0);
        uint4* dst = (uint4*)&Qs[r * ASTRIDE + c0];
#pragma unroll
        for (int j = 0; j < 4; j++) dst[j] = src[j];
    }

    const uint32_t sQ = smem_u32(Qs);
    const uint32_t sK0 = smem_u32(Kst);
    const uint32_t sV0 = smem_u32(Vst);
    const uint32_t aQ = sQ + (w * 16 + (lane & 15)) * (ASTRIDE * 2) + (lane >> 4) * 16;
    const uint32_t bKV = (((lane >> 3) & 1) * 8 + (lane & 7)) * (ASTRIDE * 2) + (lane >> 4) * 16;

    auto load_kv = [&](int kt, int st) {
#pragma unroll
        for (int j = 0; j < 4; j++) {
            int id = tid + 128 * j;
            int r = id >> 3;
            int cb = (id & 7) * 8;
            const char* gsrc = (const char*)(qkvh + ((size_t)(b * SS + kt * 64 + r)) * 3072 + h * 64 + cb);
            CP_ASYNC16(sK0 + st * KVB + r * (ASTRIDE * 2) + cb * 2, gsrc + 2048);
            CP_ASYNC16(sV0 + st * KVB + r * (ASTRIDE * 2) + cb * 2, gsrc + 4096);
        }
        CP_COMMIT();
    };

    load_kv(0, 0);

    float m0 = -1e30f, m1 = -1e30f, l0 = 0.f, l1 = 0.f;
    float o[8][4];
#pragma unroll
    for (int nt = 0; nt < 8; nt++)
#pragma unroll
        for (int j = 0; j < 4; j++) o[nt][j] = 0.f;

    const int r0 = lane >> 2;
    const int cql = (lane & 3) * 2;
    const int qg0 = qbase + w * 16 + r0;

    for (int kt = 0; kt < 16; kt++) {
        const int st = kt & 1;
        if (kt + 1 < 16) {
            load_kv(kt + 1, st ^ 1);
            CP_WAIT1();
        } else {
            CP_WAIT0();
        }
        __syncthreads();

        const uint32_t sK = sK0 + st * KVB;
        const uint32_t sV = sV0 + st * KVB;

        float s[8][4];
#pragma unroll
        for (int nt = 0; nt < 8; nt++)
#pragma unroll
            for (int j = 0; j < 4; j++) s[nt][j] = 0.f;
#pragma unroll
        for (int k16 = 0; k16 < 4; k16++) {
            uint32_t a0, a1, a2, a3;
            LDM_X4(a0, a1, a2, a3, aQ + k16 * 32);
#pragma unroll
            for (int np = 0; np < 4; np++) {
                uint32_t b0, b1, b2, b3;
                LDM_X4(b0, b1, b2, b3, sK + bKV + np * (16 * ASTRIDE * 2) + k16 * 32);
                MMA_BF16(s[np * 2],     a0, a1, a2, a3, b0, b2);
                MMA_BF16(s[np * 2 + 1], a0, a1, a2, a3, b1, b3);
            }
        }

        const int kb = kt * 64 + cql;
        float mt0 = -1e30f, mt1 = -1e30f;
#pragma unroll
        for (int nt = 0; nt < 8; nt++) {
            int kg = kb + nt * 8;
            int i00 = min(max(qg0 - kg + 63, 0), 126);
            int i01 = min(max(qg0 - kg + 62, 0), 126);
            int i10 = min(max(qg0 - kg + 71, 0), 126);
            int i11 = min(max(qg0 - kg + 70, 0), 126);
            s[nt][0] += rb[i00]; s[nt][1] += rb[i01];
            s[nt][2] += rb[i10]; s[nt][3] += rb[i11];
            mt0 = fmaxf(mt0, fmaxf(s[nt][0], s[nt][1]));
            mt1 = fmaxf(mt1, fmaxf(s[nt][2], s[nt][3]));
        }
        mt0 = fmaxf(mt0, __shfl_xor_sync(0xffffffffu, mt0, 1));
        mt0 = fmaxf(mt0, __shfl_xor_sync(0xffffffffu, mt0, 2));
        mt1 = fmaxf(mt1, __shfl_xor_sync(0xffffffffu, mt1, 1));
        mt1 = fmaxf(mt1, __shfl_xor_sync(0xffffffffu, mt1, 2));

        float mn0 = fmaxf(m0, mt0), mn1 = fmaxf(m1, mt1);
        float c0f = __expf(m0 - mn0), c1f = __expf(m1 - mn1);
        float ls0 = 0.f, ls1 = 0.f;
        uint32_t pa[4][4];
#pragma unroll
        for (int nt = 0; nt < 8; nt++) {
            float p0 = __expf(s[nt][0] - mn0);
            float p1 = __expf(s[nt][1] - mn0);
            float p2 = __expf(s[nt][2] - mn1);
            float p3 = __expf(s[nt][3] - mn1);
            ls0 += p0 + p1; ls1 += p2 + p3;
            uint32_t lo = pack_bf162(p0, p1);
            uint32_t hi = pack_bf162(p2, p3);
            if ((nt & 1) == 0) { pa[nt >> 1][0] = lo; pa[nt >> 1][1] = hi; }
            else               { pa[nt >> 1][2] = lo; pa[nt >> 1][3] = hi; }
        }
        ls0 += __shfl_xor_sync(0xffffffffu, ls0, 1);
        ls0 += __shfl_xor_sync(0xffffffffu, ls0, 2);
        ls1 += __shfl_xor_sync(0xffffffffu, ls1, 1);
        ls1 += __shfl_xor_sync(0xffffffffu, ls1, 2);
        l0 = l0 * c0f + ls0;
        l1 = l1 * c1f + ls1;
        m0 = mn0; m1 = mn1;
#pragma unroll
        for (int nt = 0; nt < 8; nt++) {
            o[nt][0] *= c0f; o[nt][1] *= c0f;
            o[nt][2] *= c1f; o[nt][3] *= c1f;
        }

#pragma unroll
        for (int kk = 0; kk < 4; kk++) {
#pragma unroll
            for (int dt = 0; dt < 4; dt++) {
                uint32_t b0, b1, b2, b3;
                LDM_X4T(b0, b1, b2, b3, sV + bKV + kk * (16 * ASTRIDE * 2) + dt * 32);
                MMA_BF16(o[dt * 2],     pa[kk][0], pa[kk][1], pa[kk][2], pa[kk][3], b0, b1);
                MMA_BF16(o[dt * 2 + 1], pa[kk][0], pa[kk][1], pa[kk][2], pa[kk][3], b2, b3);
            }
        }
        __syncthreads();
    }

    const float inv0 = 1.f / l0, inv1 = 1.f / l1;
    const int colb = h * 64 + cql;
#pragma unroll
    for (int nt = 0; nt < 8; nt++) {
        int col = colb + nt * 8;
#pragma unroll
        for (int half = 0; half < 2; half++) {
            float inv = half ? inv1 : inv0;
            float v0 = o[nt][half * 2 + 0] * inv;
            float v1 = o[nt][half * 2 + 1] * inv;
            int row = qbase + w * 16 + r0 + half * 8;
            __half2 hp;
            hp.x = __float2half_rn(v0);
            hp.y = __float2half_rn(v1);
            *(__half2*)&outs[(size_t)(b * SS + row) * DM + col] = hp;
        }
    }
}

// ---------------- residual + layernorm ----------------
template <int SPLIT>
__global__ void __launch_bounds__(256)
ln_res_kernel(const float* __restrict__ a, const float* __restrict__ r,
              const float* __restrict__ g, const float* __restrict__ bt,
              float* __restrict__ out, __half* __restrict__ outs)
{
    __shared__ float red[8];
    const int row = blockIdx.x;
    const int tid = threadIdx.x;
    const float* pa = a + (size_t)row * DM;
    const float* pr = r + (size_t)row * DM;

    float v[4];
    float sum = 0.f;
#pragma unroll
    for (int j = 0; j < 4; j++) {
        int c = tid + j * 256;
        v[j] = pa[c] + pr[c];
        sum += v[j];
    }
#pragma unroll
    for (int o = 16; o > 0; o >>= 1) sum += __shfl_xor_sync(0xffffffffu, sum, o);
    if ((tid & 31) == 0) red[tid >> 5] = sum;
    __syncthreads();
    float tot = 0.f;
#pragma unroll
    for (int ww = 0; ww < 8; ww++) tot += red[ww];
    const float mean = tot * (1.f / (float)DM);

    float sq = 0.f;
#pragma unroll
    for (int j = 0; j < 4; j++) { float dd = v[j] - mean; sq += dd * dd; }
    __syncthreads();
#pragma unroll
    for (int o = 16; o > 0; o >>= 1) sq += __shfl_xor_sync(0xffffffffu, sq, o);
    if ((tid & 31) == 0) red[tid >> 5] = sq;
    __syncthreads();
    float vtot = 0.f;
#pragma unroll
    for (int ww = 0; ww < 8; ww++) vtot += red[ww];
    const float inv = rsqrtf(vtot * (1.f / (float)DM) + 1e-5f);

#pragma unroll
    for (int j = 0; j < 4; j++) {
        int c = tid + j * 256;
        float o = (v[j] - mean) * inv * g[c] + bt[c];
        out[(size_t)row * DM + c] = o;
        if (SPLIT)
            outs[(size_t)row * DM + c] = __float2half_rn(o);
    }
}

// ---------------- host ----------------
extern "C" void kernel_launch(void* const* d_in, const int* in_sizes, int n_in,
                              void* d_out, int out_size)
{
    const float* x     = (const float*)d_in[0];
    const float* se    = (const float*)d_in[1];
    const float* qkv_w = (const float*)d_in[2];
    const float* qkv_b = (const float*)d_in[3];
    const float* out_w = (const float*)d_in[4];
    const float* out_b = (const float*)d_in[5];
    const float* rpb   = (const float*)d_in[6];
    const float* w1    = (const float*)d_in[7];
    const float* b1    = (const float*)d_in[8];
    const float* w2    = (const float*)d_in[9];
    const float* b2    = (const float*)d_in[10];
    const float* ln1g  = (const float*)d_in[11];
    const float* ln1b  = (const float*)d_in[12];
    const float* ln2g  = (const float*)d_in[13];
    const float* ln2b  = (const float*)d_in[14];
    const int*   ts    = (const int*)d_in[15];
    float* out = (float*)d_out;

    float *x0, *proj, *x1, *ffn;
    __nv_bfloat16 *qkvh;
    __half *x0s, *attns, *x1s, *hs, *wqkvs, *wouts, *w1s, *w2s;
    cudaGetSymbolAddress((void**)&x0,   g_x0);
    cudaGetSymbolAddress((void**)&qkvh, g_qkvh);
    cudaGetSymbolAddress((void**)&proj, g_proj);
    cudaGetSymbolAddress((void**)&x1,   g_x1);
    cudaGetSymbolAddress((void**)&ffn,  g_ffn);
    cudaGetSymbolAddress((void**)&x0s,   g_x0s);
    cudaGetSymbolAddress((void**)&attns, g_attns);
    cudaGetSymbolAddress((void**)&x1s,   g_x1s);
    cudaGetSymbolAddress((void**)&hs,    g_hs);
    cudaGetSymbolAddress((void**)&wqkvs, g_wqkvs);
    cudaGetSymbolAddress((void**)&wouts, g_wouts);
    cudaGetSymbolAddress((void**)&w1s,   g_w1s);
    cudaGetSymbolAddress((void**)&w2s,   g_w2s);

    cudaFuncSetAttribute(gemm_mma<0>, cudaFuncAttributeMaxDynamicSharedMemorySize, GSMEM);
    cudaFuncSetAttribute(gemm_mma<1>, cudaFuncAttributeMaxDynamicSharedMemorySize, GSMEM);
    cudaFuncSetAttribute(gemm_mma<2>, cudaFuncAttributeMaxDynamicSharedMemorySize, GSMEM);

    // fused prep: add_step + all weight conversions, one launch
    prep_kernel<<<PREP_BLOCKS, 256>>>(x, se, ts, x0, x0s,
                                      qkv_w, out_w, w1, w2,
                                      wqkvs, wouts, w1s, w2s);

    gemm_mma<2><<<dim3(3 * DM / 128, MTOK / 128), 256, GSMEM>>>(
        x0s, wqkvs, qkv_b, nullptr, qkvh, 3 * DM, DM);

    attn_mma_kernel<<<dim3(SS / 64, NH, BB), 128>>>(qkvh, rpb, attns);

    gemm_mma<0><<<dim3(DM / 128, MTOK / 128), 256, GSMEM>>>(
        attns, wouts, out_b, proj, nullptr, DM, DM);

    ln_res_kernel<1><<<MTOK, 256>>>(x0, proj, ln1g, ln1b, x1, x1s);

    gemm_mma<1><<<dim3(DFF / 128, MTOK / 128), 256, GSMEM>>>(
        x1s, w1s, b1, nullptr, hs, DFF, DM);

    gemm_mma<0><<<dim3(DM / 128, MTOK / 128), 256, GSMEM>>>(
        hs, w2s, b2, ffn, nullptr, DM, DFF);

    ln_res_kernel<0><<<MTOK, 256>>>(x1, ffn, ln2g, ln2b, out, nullptr);
}